// round 12
// baseline (speedup 1.0000x reference)
#include <cuda_runtime.h>
#include <math_constants.h>

#define N_MAX 30000
#define M_MAX 10000
#define G     32
#define NC    (G * G * G)          // 32768 cells per grid
#define NCT   (2 * NC)             // grid 0: Ps (A targets); grid 1: P (B targets)
#define LHALF 4.0f                 // domain [-4, 4]^3 (coords clamped into edge cells)
#define CELLH 0.25f
#define INVH  4.0f

#define SCAN_T   1024
#define SCAN_NB  (NCT / SCAN_T)    // 64 blocks, one cell per thread

// Device scratch (zero-init at load; self-cleaning across graph replays).
__device__ unsigned int g_counts[NCT];        // reset inside scan_kernel
__device__ uint2        g_meta[NCT];          // (block-local excl prefix, count)
__device__ unsigned int g_blockSum[SCAN_NB];
__device__ unsigned int g_blockOff[SCAN_NB];  // exclusive offsets of blocks
__device__ unsigned int g_cursor[NCT];        // reset by reduce_kernel
__device__ float4       g_sp[N_MAX + M_MAX];  // sorted points, .w = orig index bits
__device__ float        g_term[N_MAX + M_MAX];
#define NB_RED 40
__device__ float g_partials[NB_RED];
__device__ int   g_scan_done = 0;             // arrival counters; self-reset
__device__ int   g_done = 0;

// ---------------------------------------------------------------------------
__device__ __forceinline__ int cellCoord(float x) {
    int c = (int)floorf((x + LHALF) * INVH);
    return min(max(c, 0), G - 1);
}
__device__ __forceinline__ int cellOf(float x, float y, float z) {
    return (cellCoord(z) * G + cellCoord(y)) * G + cellCoord(x);
}
// cell -> [start,end) in the sorted array
__device__ __forceinline__ uint2 cellRange(int c) {
    const unsigned int off = g_blockOff[c >> 10];
    const uint2 mt = g_meta[c];
    return make_uint2(off + mt.x, off + mt.x + mt.y);
}

// ---------------------------------------------------------------------------
// 1) count points per cell (both grids)
// ---------------------------------------------------------------------------
__global__ void count_kernel(const float* __restrict__ P,
                             const float* __restrict__ Ps, int n, int m) {
    int i = blockIdx.x * blockDim.x + threadIdx.x;
    if (i < m) {
        const float* q = Ps + 3 * i;
        atomicAdd(&g_counts[cellOf(q[0], q[1], q[2])], 1u);
    } else if (i < m + n) {
        const float* p = P + 3 * (i - m);
        atomicAdd(&g_counts[NC + cellOf(p[0], p[1], p[2])], 1u);
    }
}

// ---------------------------------------------------------------------------
// 2) fused two-level exclusive scan: 64 blocks do block-local scans; the
//    last-arriving block scans the 64 block sums.  Counts reset for replay.
// ---------------------------------------------------------------------------
__global__ __launch_bounds__(SCAN_T) void scan_kernel() {
    __shared__ unsigned int ssum[SCAN_T];
    __shared__ bool isLast;
    const int t = threadIdx.x;
    const int c = blockIdx.x * SCAN_T + t;

    const unsigned int cnt = g_counts[c];
    g_counts[c] = 0u;                     // clean for next replay
    ssum[t] = cnt;
    __syncthreads();

    for (int off = 1; off < SCAN_T; off <<= 1) {
        unsigned int v = (t >= off) ? ssum[t - off] : 0u;
        __syncthreads();
        ssum[t] += v;
        __syncthreads();
    }
    g_meta[c] = make_uint2(ssum[t] - cnt, cnt);     // exclusive local prefix
    if (t == SCAN_T - 1) g_blockSum[blockIdx.x] = ssum[t];

    if (t == 0) {
        __threadfence();
        isLast = (atomicAdd(&g_scan_done, 1) == (int)gridDim.x - 1);
    }
    __syncthreads();

    if (isLast) {
        __threadfence();
        volatile unsigned int* bs = g_blockSum;
        unsigned int v = (t < SCAN_NB) ? bs[t] : 0u;
        ssum[t] = v;
        __syncthreads();
        for (int off = 1; off < SCAN_NB; off <<= 1) {
            unsigned int w = (t >= off && t < SCAN_NB) ? ssum[t - off] : 0u;
            __syncthreads();
            if (t < SCAN_NB) ssum[t] += w;
            __syncthreads();
        }
        if (t < SCAN_NB) g_blockOff[t] = ssum[t] - v;   // exclusive
        if (t == 0) g_scan_done = 0;
    }
}

// ---------------------------------------------------------------------------
// 3) scatter points into sorted slots (order nondeterministic; consumers are
//    order-invariant: exact u64 (d2,idx) mins and per-slot writes).
// ---------------------------------------------------------------------------
__global__ void scatter_kernel(const float* __restrict__ P,
                               const float* __restrict__ Ps, int n, int m) {
    int i = blockIdx.x * blockDim.x + threadIdx.x;
    if (i < m) {
        float x = Ps[3 * i], y = Ps[3 * i + 1], z = Ps[3 * i + 2];
        int c = cellOf(x, y, z);
        unsigned int slot = g_blockOff[c >> 10] + g_meta[c].x +
                            atomicAdd(&g_cursor[c], 1u);
        g_sp[slot] = make_float4(x, y, z, __uint_as_float((unsigned int)i));
    } else if (i < m + n) {
        int j = i - m;
        float x = P[3 * j], y = P[3 * j + 1], z = P[3 * j + 2];
        int c = NC + cellOf(x, y, z);
        unsigned int slot = g_blockOff[c >> 10] + g_meta[c].x +
                            atomicAdd(&g_cursor[c], 1u);
        g_sp[slot] = make_float4(x, y, z, __uint_as_float((unsigned int)j));
    }
}

// ---------------------------------------------------------------------------
// 4) nearest-neighbor query: ONE WARP PER QUERY, candidate-parallel lanes.
//    Phase 1: 3x3x3 box of h=0.25 cells = 9 contiguous row-runs; lanes
//             stride candidates within each run (coalesced LDG.128).
//    Phase 2: rings s>=2 (rare: ~3% tail queries).
//    Ring bound: d >= (s-1)*h - o  (o = query overflow beyond clamped domain).
// ---------------------------------------------------------------------------
__global__ __launch_bounds__(256)
void query_kernel(const float* __restrict__ prob, int n, int m) {
    const int w = (blockIdx.x * blockDim.x + threadIdx.x) >> 5;
    const int lane = threadIdx.x & 31;
    const int total = n + m;
    if (w >= total) return;

    const float4 q = g_sp[w];
    const bool isB = (w < m);
    const int cbase = isB ? NC : 0;

    const int cx = cellCoord(q.x), cy = cellCoord(q.y), cz = cellCoord(q.z);
    const float o = fmaxf(fmaxf(fabsf(q.x), fmaxf(fabsf(q.y), fabsf(q.z))) - LHALF, 0.0f);

    unsigned long long best = 0xFFFFFFFFFFFFFFFFull;   // (d2_bits<<32)|idx

    // ---- Phase 1: 3x3x3 box, rows of contiguous slots, lanes over candidates
    {
        const int x0 = max(cx - 1, 0), x1 = min(cx + 1, G - 1);
        const int y0 = max(cy - 1, 0), y1 = min(cy + 1, G - 1);
        const int z0 = max(cz - 1, 0), z1 = min(cz + 1, G - 1);

        for (int iz = z0; iz <= z1; iz++) {
            for (int iy = y0; iy <= y1; iy++) {
                const int rowb = cbase + (iz * G + iy) * G;
                const unsigned int off = g_blockOff[(rowb + x0) >> 10];
                const uint2 m0 = g_meta[rowb + x0];
                const uint2 m1 = g_meta[rowb + x1];
                const unsigned int r0 = off + m0.x;
                const unsigned int r1 = off + m1.x + m1.y;
                for (unsigned int v = r0 + lane; v < r1; v += 32) {
                    const float4 tp = g_sp[v];      // coalesced across lanes
                    float ddx = q.x - tp.x;
                    float ddy = q.y - tp.y;
                    float ddz = q.z - tp.z;
                    float d2 = fmaf(ddx, ddx, fmaf(ddy, ddy, ddz * ddz));
                    unsigned long long pk =
                        ((unsigned long long)__float_as_uint(d2) << 32) |
                        (unsigned long long)__float_as_uint(tp.w);
                    if (pk < best) best = pk;
                }
            }
        }
        #pragma unroll
        for (int off = 16; off > 0; off >>= 1) {
            unsigned long long ob = __shfl_xor_sync(0xFFFFFFFFu, best, off);
            if (ob < best) best = ob;
        }
    }
    float bestd2 = __uint_as_float((unsigned int)(best >> 32));

    // ---- Phase 2: expanding rings s>=2 (rare path)
    for (int s = 2; s < G; s++) {
        float b = (float)(s - 1) * CELLH * 0.999f - o;
        if (b > 0.0f && b * b > bestd2) break;

        const int side = 2 * s + 1;
        const int box = side * side * side;
        for (int t = lane; t < box; t += 32) {
            int dz = t / (side * side);
            int rem = t - dz * side * side;
            int dy = rem / side;
            int dx = rem - dy * side;
            dz -= s; dy -= s; dx -= s;
            if (max(abs(dx), max(abs(dy), abs(dz))) != s) continue;   // shell only
            const int ix = cx + dx, iy = cy + dy, iz = cz + dz;
            if (ix < 0 || ix >= G || iy < 0 || iy >= G || iz < 0 || iz >= G) continue;
            const uint2 r = cellRange(cbase + (iz * G + iy) * G + ix);
            for (unsigned int v = r.x; v < r.y; v++) {
                const float4 tp = g_sp[v];
                float ddx = q.x - tp.x;
                float ddy = q.y - tp.y;
                float ddz = q.z - tp.z;
                float d2 = fmaf(ddx, ddx, fmaf(ddy, ddy, ddz * ddz));
                unsigned long long pk =
                    ((unsigned long long)__float_as_uint(d2) << 32) |
                    (unsigned long long)__float_as_uint(tp.w);
                if (pk < best) best = pk;
            }
        }
        #pragma unroll
        for (int off = 16; off > 0; off >>= 1) {
            unsigned long long ob = __shfl_xor_sync(0xFFFFFFFFu, best, off);
            if (ob < best) best = ob;
        }
        bestd2 = __uint_as_float((unsigned int)(best >> 32));
    }

    if (lane == 0) {
        const float d = sqrtf(__uint_as_float((unsigned int)(best >> 32)));
        const unsigned int widx = (unsigned int)(best & 0xFFFFFFFFu);
        const unsigned int qorig = __float_as_uint(q.w);
        if (isB) {
            g_term[qorig] = d * __ldg(&prob[qorig]);      // s->o term
        } else {
            g_term[m + qorig] = d * __ldg(&prob[widx]);   // o->s term
        }
    }
}

// ---------------------------------------------------------------------------
// 5) deterministic fixed-order sum + fused final; resets cursors for replay.
// ---------------------------------------------------------------------------
__global__ __launch_bounds__(256)
void reduce_kernel(int total, float* __restrict__ out) {
    __shared__ float ssum[256];
    __shared__ bool isLast;
    const int stride = gridDim.x * blockDim.x;
    const int tid0 = blockIdx.x * blockDim.x + threadIdx.x;

    // reset scatter cursors for the next graph replay
    for (int i = tid0; i < NCT; i += stride) g_cursor[i] = 0u;

    float sum = 0.0f;
    for (int i = tid0; i < total; i += stride)
        sum += g_term[i];

    ssum[threadIdx.x] = sum;
    __syncthreads();
    for (int off = 128; off > 0; off >>= 1) {
        if (threadIdx.x < off) ssum[threadIdx.x] += ssum[threadIdx.x + off];
        __syncthreads();
    }
    if (threadIdx.x == 0) {
        g_partials[blockIdx.x] = ssum[0];
        __threadfence();
        int t = atomicAdd(&g_done, 1);
        isLast = (t == (int)gridDim.x - 1);
    }
    __syncthreads();

    if (isLast) {
        __threadfence();
        volatile float* gp = g_partials;
        float v = (threadIdx.x < (int)gridDim.x) ? gp[threadIdx.x] : 0.0f;
        ssum[threadIdx.x] = v;
        __syncthreads();
        for (int off = 128; off > 0; off >>= 1) {
            if (threadIdx.x < off) ssum[threadIdx.x] += ssum[threadIdx.x + off];
            __syncthreads();
        }
        if (threadIdx.x == 0) {
            out[0] = ssum[0];
            g_done = 0;
        }
    }
}

// ---------------------------------------------------------------------------
// Launch: 5 kernels.
// ---------------------------------------------------------------------------
extern "C" void kernel_launch(void* const* d_in, const int* in_sizes, int n_in,
                              void* d_out, int out_size) {
    const float* P    = (const float*)d_in[0];
    const float* Ps   = (const float*)d_in[1];
    const float* prob = (const float*)d_in[2];
    float* out = (float*)d_out;

    const int n = in_sizes[0] / 3;   // 30000
    const int m = in_sizes[1] / 3;   // 10000
    const int total = n + m;
    const int nb = (total + 255) / 256;

    count_kernel<<<nb, 256>>>(P, Ps, n, m);
    scan_kernel<<<SCAN_NB, SCAN_T>>>();
    scatter_kernel<<<nb, 256>>>(P, Ps, n, m);
    query_kernel<<<(total * 32 + 255) / 256, 256>>>(prob, n, m);
    reduce_kernel<<<NB_RED, 256>>>(total, out);
}

// round 13
// speedup vs baseline: 1.7016x; 1.7016x over previous
#include <cuda_runtime.h>
#include <math_constants.h>

#define N_MAX 30000
#define M_MAX 10000
#define LHALF 4.0f                  // domain [-4,4]^3, coords clamped to edge cells

// Grid A: targets = Ps (sparse, 10k) -> coarser cells
#define GA     24
#define NCA    (GA * GA * GA)       // 13824
#define INVHA  3.0f
#define CELLHA (1.0f / 3.0f)
// Grid B: targets = P (dense, 30k) -> finer cells
#define GB     32
#define NCB    (GB * GB * GB)       // 32768
#define INVHB  4.0f
#define CELLHB 0.25f

#define NCT      (NCA + NCB)        // 46592 real cells
#define SCAN_T   1024
#define SCAN_NB  46                 // 46*1024 = 47104 padded cells
#define NCT_PAD  (SCAN_NB * SCAN_T)

// Device scratch (zero-init at load; self-cleaning across graph replays).
__device__ unsigned int g_counts[NCT_PAD];     // reset inside scan_kernel
__device__ uint2        g_meta[NCT_PAD];       // (block-local excl prefix, count)
__device__ unsigned int g_blockSum[SCAN_NB];
__device__ unsigned int g_blockOff[SCAN_NB];
__device__ unsigned int g_cursor[NCT_PAD];     // reset by reduce_kernel
__device__ float4       g_sp[N_MAX + M_MAX];   // sorted points, .w = orig index bits
__device__ float        g_term[N_MAX + M_MAX];
#define NB_RED 40
__device__ float g_partials[NB_RED];
__device__ int   g_scan_done = 0;              // arrival counters; self-reset
__device__ int   g_done = 0;

// ---------------------------------------------------------------------------
__device__ __forceinline__ int cellCoordG(float x, float invh, int Gq) {
    int c = (int)floorf((x + LHALF) * invh);
    return min(max(c, 0), Gq - 1);
}
__device__ __forceinline__ int cellA(float x, float y, float z) {
    return (cellCoordG(z, INVHA, GA) * GA + cellCoordG(y, INVHA, GA)) * GA
           + cellCoordG(x, INVHA, GA);
}
__device__ __forceinline__ int cellB(float x, float y, float z) {
    return (cellCoordG(z, INVHB, GB) * GB + cellCoordG(y, INVHB, GB)) * GB
           + cellCoordG(x, INVHB, GB);
}
// cell -> [start,end) in the sorted array (two-level scan reconstruction)
__device__ __forceinline__ uint2 cellRange(int c) {
    const unsigned int off = g_blockOff[c >> 10];
    const uint2 mt = g_meta[c];
    return make_uint2(off + mt.x, off + mt.x + mt.y);
}

// ---------------------------------------------------------------------------
// 1) count points per cell.  Ps -> grid A (slots first), P -> grid B.
// ---------------------------------------------------------------------------
__global__ void count_kernel(const float* __restrict__ P,
                             const float* __restrict__ Ps, int n, int m) {
    int i = blockIdx.x * blockDim.x + threadIdx.x;
    if (i < m) {
        const float* q = Ps + 3 * i;
        atomicAdd(&g_counts[cellA(q[0], q[1], q[2])], 1u);
    } else if (i < m + n) {
        const float* p = P + 3 * (i - m);
        atomicAdd(&g_counts[NCA + cellB(p[0], p[1], p[2])], 1u);
    }
}

// ---------------------------------------------------------------------------
// 2) fused two-level exclusive scan over the padded flat cell array.
// ---------------------------------------------------------------------------
__global__ __launch_bounds__(SCAN_T) void scan_kernel() {
    __shared__ unsigned int ssum[SCAN_T];
    __shared__ bool isLast;
    const int t = threadIdx.x;
    const int c = blockIdx.x * SCAN_T + t;

    const unsigned int cnt = g_counts[c];
    g_counts[c] = 0u;                     // clean for next replay
    ssum[t] = cnt;
    __syncthreads();

    for (int off = 1; off < SCAN_T; off <<= 1) {
        unsigned int v = (t >= off) ? ssum[t - off] : 0u;
        __syncthreads();
        ssum[t] += v;
        __syncthreads();
    }
    g_meta[c] = make_uint2(ssum[t] - cnt, cnt);
    if (t == SCAN_T - 1) g_blockSum[blockIdx.x] = ssum[t];

    if (t == 0) {
        __threadfence();
        isLast = (atomicAdd(&g_scan_done, 1) == (int)gridDim.x - 1);
    }
    __syncthreads();

    if (isLast) {
        __threadfence();
        volatile unsigned int* bs = g_blockSum;
        unsigned int v = (t < SCAN_NB) ? bs[t] : 0u;
        ssum[t] = v;
        __syncthreads();
        for (int off = 1; off < SCAN_NB; off <<= 1) {
            unsigned int w = (t >= off && t < SCAN_NB) ? ssum[t - off] : 0u;
            __syncthreads();
            if (t < SCAN_NB) ssum[t] += w;
            __syncthreads();
        }
        if (t < SCAN_NB) g_blockOff[t] = ssum[t] - v;
        if (t == 0) g_scan_done = 0;
    }
}

// ---------------------------------------------------------------------------
// 3) scatter into sorted slots.  Ps occupy [0,m), P occupy [m,m+n).
// ---------------------------------------------------------------------------
__global__ void scatter_kernel(const float* __restrict__ P,
                               const float* __restrict__ Ps, int n, int m) {
    int i = blockIdx.x * blockDim.x + threadIdx.x;
    if (i < m) {
        float x = Ps[3 * i], y = Ps[3 * i + 1], z = Ps[3 * i + 2];
        int c = cellA(x, y, z);
        unsigned int slot = g_blockOff[c >> 10] + g_meta[c].x +
                            atomicAdd(&g_cursor[c], 1u);
        g_sp[slot] = make_float4(x, y, z, __uint_as_float((unsigned int)i));
    } else if (i < m + n) {
        int j = i - m;
        float x = P[3 * j], y = P[3 * j + 1], z = P[3 * j + 2];
        int c = NCA + cellB(x, y, z);
        unsigned int slot = g_blockOff[c >> 10] + g_meta[c].x +
                            atomicAdd(&g_cursor[c], 1u);
        g_sp[slot] = make_float4(x, y, z, __uint_as_float((unsigned int)j));
    }
}

// ---------------------------------------------------------------------------
// 4) nearest-neighbor query: ONE WARP PER QUERY.
//    w <  m : Ps point, min-only, searches grid B (float path).
//    w >= m : P point, min+argmin, searches grid A (u64 path).
//    Phase 1: 3x3x3 box; row metadata prefetched by lanes 0..8, broadcast by
//             shfl; lanes stride candidates in each contiguous row-run.
//    Phase 2: expanding rings (rare, density-matched grids keep it ~2%).
// ---------------------------------------------------------------------------
__global__ __launch_bounds__(256)
void query_kernel(const float* __restrict__ prob, int n, int m) {
    const int w = (blockIdx.x * blockDim.x + threadIdx.x) >> 5;
    const int lane = threadIdx.x & 31;
    const int total = n + m;
    if (w >= total) return;

    const float4 q = g_sp[w];
    const bool isB = (w < m);

    const int   Gq   = isB ? GB : GA;
    const float invh = isB ? INVHB : INVHA;
    const float h    = isB ? CELLHB : CELLHA;
    const int   tbase = isB ? NCA : 0;

    const int cx = cellCoordG(q.x, invh, Gq);
    const int cy = cellCoordG(q.y, invh, Gq);
    const int cz = cellCoordG(q.z, invh, Gq);
    const float o = fmaxf(fmaxf(fabsf(q.x), fmaxf(fabsf(q.y), fabsf(q.z))) - LHALF, 0.0f);

    // ---- Phase 1 metadata prefetch: 9 row ranges via lanes 0..8
    const int x0 = max(cx - 1, 0), x1 = min(cx + 1, Gq - 1);
    const int y0 = max(cy - 1, 0), y1 = min(cy + 1, Gq - 1);
    const int z0 = max(cz - 1, 0), z1 = min(cz + 1, Gq - 1);
    const int ny = y1 - y0 + 1;
    const int nrows = (z1 - z0 + 1) * ny;

    unsigned int rr0 = 0, rr1 = 0;
    if (lane < nrows) {
        const int rz = lane / ny;
        const int ry = lane - rz * ny;
        const int rowb = tbase + ((z0 + rz) * Gq + (y0 + ry)) * Gq;
        rr0 = cellRange(rowb + x0).x;
        rr1 = cellRange(rowb + x1).y;
    }

    if (isB) {
        // ================= min-only (float) =================
        float best = CUDART_INF_F;
        for (int j = 0; j < nrows; j++) {
            const unsigned int r0 = __shfl_sync(0xFFFFFFFFu, rr0, j);
            const unsigned int r1 = __shfl_sync(0xFFFFFFFFu, rr1, j);
            for (unsigned int v = r0 + lane; v < r1; v += 32) {
                const float4 tp = g_sp[v];
                float ddx = q.x - tp.x;
                float ddy = q.y - tp.y;
                float ddz = q.z - tp.z;
                best = fminf(best, fmaf(ddx, ddx, fmaf(ddy, ddy, ddz * ddz)));
            }
        }
        #pragma unroll
        for (int off = 16; off > 0; off >>= 1)
            best = fminf(best, __shfl_xor_sync(0xFFFFFFFFu, best, off));

        // Phase 2 rings (rare)
        for (int s = 2; s < Gq; s++) {
            float b = (float)(s - 1) * h * 0.999f - o;
            if (b > 0.0f && b * b > best) break;
            const int side = 2 * s + 1;
            const int box = side * side * side;
            for (int t = lane; t < box; t += 32) {
                int dz = t / (side * side);
                int rem = t - dz * side * side;
                int dy = rem / side;
                int dx = rem - dy * side;
                dz -= s; dy -= s; dx -= s;
                if (max(abs(dx), max(abs(dy), abs(dz))) != s) continue;
                const int ix = cx + dx, iy = cy + dy, iz = cz + dz;
                if (ix < 0 || ix >= Gq || iy < 0 || iy >= Gq ||
                    iz < 0 || iz >= Gq) continue;
                const uint2 r = cellRange(tbase + (iz * Gq + iy) * Gq + ix);
                for (unsigned int v = r.x; v < r.y; v++) {
                    const float4 tp = g_sp[v];
                    float ddx = q.x - tp.x;
                    float ddy = q.y - tp.y;
                    float ddz = q.z - tp.z;
                    best = fminf(best, fmaf(ddx, ddx, fmaf(ddy, ddy, ddz * ddz)));
                }
            }
            #pragma unroll
            for (int off = 16; off > 0; off >>= 1)
                best = fminf(best, __shfl_xor_sync(0xFFFFFFFFu, best, off));
        }

        if (lane == 0) {
            const unsigned int qorig = __float_as_uint(q.w);
            g_term[qorig] = sqrtf(best) * __ldg(&prob[qorig]);   // s->o term
        }
    } else {
        // ================= min + argmin (u64 packed) =================
        unsigned long long best = 0xFFFFFFFFFFFFFFFFull;   // (d2_bits<<32)|idx
        for (int j = 0; j < nrows; j++) {
            const unsigned int r0 = __shfl_sync(0xFFFFFFFFu, rr0, j);
            const unsigned int r1 = __shfl_sync(0xFFFFFFFFu, rr1, j);
            for (unsigned int v = r0 + lane; v < r1; v += 32) {
                const float4 tp = g_sp[v];
                float ddx = q.x - tp.x;
                float ddy = q.y - tp.y;
                float ddz = q.z - tp.z;
                float d2 = fmaf(ddx, ddx, fmaf(ddy, ddy, ddz * ddz));
                unsigned long long pk =
                    ((unsigned long long)__float_as_uint(d2) << 32) |
                    (unsigned long long)__float_as_uint(tp.w);
                if (pk < best) best = pk;
            }
        }
        #pragma unroll
        for (int off = 16; off > 0; off >>= 1) {
            unsigned long long ob = __shfl_xor_sync(0xFFFFFFFFu, best, off);
            if (ob < best) best = ob;
        }
        float bestd2 = __uint_as_float((unsigned int)(best >> 32));

        for (int s = 2; s < Gq; s++) {
            float b = (float)(s - 1) * h * 0.999f - o;
            if (b > 0.0f && b * b > bestd2) break;
            const int side = 2 * s + 1;
            const int box = side * side * side;
            for (int t = lane; t < box; t += 32) {
                int dz = t / (side * side);
                int rem = t - dz * side * side;
                int dy = rem / side;
                int dx = rem - dy * side;
                dz -= s; dy -= s; dx -= s;
                if (max(abs(dx), max(abs(dy), abs(dz))) != s) continue;
                const int ix = cx + dx, iy = cy + dy, iz = cz + dz;
                if (ix < 0 || ix >= Gq || iy < 0 || iy >= Gq ||
                    iz < 0 || iz >= Gq) continue;
                const uint2 r = cellRange(tbase + (iz * Gq + iy) * Gq + ix);
                for (unsigned int v = r.x; v < r.y; v++) {
                    const float4 tp = g_sp[v];
                    float ddx = q.x - tp.x;
                    float ddy = q.y - tp.y;
                    float ddz = q.z - tp.z;
                    float d2 = fmaf(ddx, ddx, fmaf(ddy, ddy, ddz * ddz));
                    unsigned long long pk =
                        ((unsigned long long)__float_as_uint(d2) << 32) |
                        (unsigned long long)__float_as_uint(tp.w);
                    if (pk < best) best = pk;
                }
            }
            #pragma unroll
            for (int off = 16; off > 0; off >>= 1) {
                unsigned long long ob = __shfl_xor_sync(0xFFFFFFFFu, best, off);
                if (ob < best) best = ob;
            }
            bestd2 = __uint_as_float((unsigned int)(best >> 32));
        }

        if (lane == 0) {
            const float d = sqrtf(__uint_as_float((unsigned int)(best >> 32)));
            const unsigned int widx = (unsigned int)(best & 0xFFFFFFFFu);
            const unsigned int qorig = __float_as_uint(q.w);
            g_term[m + qorig] = d * __ldg(&prob[widx]);          // o->s term
        }
    }
}

// ---------------------------------------------------------------------------
// 5) deterministic fixed-order sum + fused final; resets cursors for replay.
// ---------------------------------------------------------------------------
__global__ __launch_bounds__(256)
void reduce_kernel(int total, float* __restrict__ out) {
    __shared__ float ssum[256];
    __shared__ bool isLast;
    const int stride = gridDim.x * blockDim.x;
    const int tid0 = blockIdx.x * blockDim.x + threadIdx.x;

    for (int i = tid0; i < NCT_PAD; i += stride) g_cursor[i] = 0u;

    float sum = 0.0f;
    for (int i = tid0; i < total; i += stride)
        sum += g_term[i];

    ssum[threadIdx.x] = sum;
    __syncthreads();
    for (int off = 128; off > 0; off >>= 1) {
        if (threadIdx.x < off) ssum[threadIdx.x] += ssum[threadIdx.x + off];
        __syncthreads();
    }
    if (threadIdx.x == 0) {
        g_partials[blockIdx.x] = ssum[0];
        __threadfence();
        int t = atomicAdd(&g_done, 1);
        isLast = (t == (int)gridDim.x - 1);
    }
    __syncthreads();

    if (isLast) {
        __threadfence();
        volatile float* gp = g_partials;
        float v = (threadIdx.x < (int)gridDim.x) ? gp[threadIdx.x] : 0.0f;
        ssum[threadIdx.x] = v;
        __syncthreads();
        for (int off = 128; off > 0; off >>= 1) {
            if (threadIdx.x < off) ssum[threadIdx.x] += ssum[threadIdx.x + off];
            __syncthreads();
        }
        if (threadIdx.x == 0) {
            out[0] = ssum[0];
            g_done = 0;
        }
    }
}

// ---------------------------------------------------------------------------
// Launch: 5 kernels.
// ---------------------------------------------------------------------------
extern "C" void kernel_launch(void* const* d_in, const int* in_sizes, int n_in,
                              void* d_out, int out_size) {
    const float* P    = (const float*)d_in[0];
    const float* Ps   = (const float*)d_in[1];
    const float* prob = (const float*)d_in[2];
    float* out = (float*)d_out;

    const int n = in_sizes[0] / 3;   // 30000
    const int m = in_sizes[1] / 3;   // 10000
    const int total = n + m;
    const int nb = (total + 255) / 256;

    count_kernel<<<nb, 256>>>(P, Ps, n, m);
    scan_kernel<<<SCAN_NB, SCAN_T>>>();
    scatter_kernel<<<nb, 256>>>(P, Ps, n, m);
    query_kernel<<<(total * 32 + 255) / 256, 256>>>(prob, n, m);
    reduce_kernel<<<NB_RED, 256>>>(total, out);
}

// round 14
// speedup vs baseline: 2.4362x; 1.4317x over previous
#include <cuda_runtime.h>
#include <math_constants.h>

#define N_MAX 30000
#define M_MAX 10000
#define LHALF 4.0f                  // domain [-4,4]^3, coords clamped to edge cells

// Grid A: targets = Ps (sparse, 10k) -> coarser cells
#define GA     24
#define NCA    (GA * GA * GA)       // 13824
#define INVHA  3.0f
#define CELLHA (1.0f / 3.0f)
// Grid B: targets = P (dense, 30k) -> finer cells
#define GB     32
#define NCB    (GB * GB * GB)       // 32768
#define INVHB  4.0f
#define CELLHB 0.25f

#define NCT      (NCA + NCB)        // 46592 real cells
#define SCAN_T   1024
#define SCAN_NB  46                 // 46*1024 = 47104 padded cells
#define NCT_PAD  (SCAN_NB * SCAN_T)

// Device scratch (zero-init at load; self-cleaning across graph replays).
__device__ unsigned int g_counts[NCT_PAD];     // reset inside scan_kernel
__device__ uint2        g_meta[NCT_PAD];       // (block-local excl prefix, count)
__device__ unsigned int g_blockSum[SCAN_NB];
__device__ unsigned int g_blockOff[SCAN_NB];
__device__ unsigned int g_cursor[NCT_PAD];     // reset by reduce_kernel
__device__ float4       g_sp[N_MAX + M_MAX];   // sorted points, .w = orig index bits
__device__ float        g_term[N_MAX + M_MAX];
#define NB_RED 40
__device__ float g_partials[NB_RED];
__device__ int   g_scan_done = 0;              // arrival counters; self-reset
__device__ int   g_done = 0;

// ---------------------------------------------------------------------------
__device__ __forceinline__ int cellCoordG(float x, float invh, int Gq) {
    int c = (int)floorf((x + LHALF) * invh);
    return min(max(c, 0), Gq - 1);
}
__device__ __forceinline__ int cellA(float x, float y, float z) {
    return (cellCoordG(z, INVHA, GA) * GA + cellCoordG(y, INVHA, GA)) * GA
           + cellCoordG(x, INVHA, GA);
}
__device__ __forceinline__ int cellB(float x, float y, float z) {
    return (cellCoordG(z, INVHB, GB) * GB + cellCoordG(y, INVHB, GB)) * GB
           + cellCoordG(x, INVHB, GB);
}
// cell -> [start,end) in the sorted array (two-level scan reconstruction)
__device__ __forceinline__ uint2 cellRange(int c) {
    const unsigned int off = g_blockOff[c >> 10];
    const uint2 mt = g_meta[c];
    return make_uint2(off + mt.x, off + mt.x + mt.y);
}

// ---------------------------------------------------------------------------
// 1) count points per cell.  Ps -> grid A (slots first), P -> grid B.
// ---------------------------------------------------------------------------
__global__ void count_kernel(const float* __restrict__ P,
                             const float* __restrict__ Ps, int n, int m) {
    int i = blockIdx.x * blockDim.x + threadIdx.x;
    if (i < m) {
        const float* q = Ps + 3 * i;
        atomicAdd(&g_counts[cellA(q[0], q[1], q[2])], 1u);
    } else if (i < m + n) {
        const float* p = P + 3 * (i - m);
        atomicAdd(&g_counts[NCA + cellB(p[0], p[1], p[2])], 1u);
    }
}

// ---------------------------------------------------------------------------
// 2) fused two-level exclusive scan over the padded flat cell array.
// ---------------------------------------------------------------------------
__global__ __launch_bounds__(SCAN_T) void scan_kernel() {
    __shared__ unsigned int ssum[SCAN_T];
    __shared__ bool isLast;
    const int t = threadIdx.x;
    const int c = blockIdx.x * SCAN_T + t;

    const unsigned int cnt = g_counts[c];
    g_counts[c] = 0u;                     // clean for next replay
    ssum[t] = cnt;
    __syncthreads();

    for (int off = 1; off < SCAN_T; off <<= 1) {
        unsigned int v = (t >= off) ? ssum[t - off] : 0u;
        __syncthreads();
        ssum[t] += v;
        __syncthreads();
    }
    g_meta[c] = make_uint2(ssum[t] - cnt, cnt);
    if (t == SCAN_T - 1) g_blockSum[blockIdx.x] = ssum[t];

    if (t == 0) {
        __threadfence();
        isLast = (atomicAdd(&g_scan_done, 1) == (int)gridDim.x - 1);
    }
    __syncthreads();

    if (isLast) {
        __threadfence();
        volatile unsigned int* bs = g_blockSum;
        unsigned int v = (t < SCAN_NB) ? bs[t] : 0u;
        ssum[t] = v;
        __syncthreads();
        for (int off = 1; off < SCAN_NB; off <<= 1) {
            unsigned int w = (t >= off && t < SCAN_NB) ? ssum[t - off] : 0u;
            __syncthreads();
            if (t < SCAN_NB) ssum[t] += w;
            __syncthreads();
        }
        if (t < SCAN_NB) g_blockOff[t] = ssum[t] - v;
        if (t == 0) g_scan_done = 0;
    }
}

// ---------------------------------------------------------------------------
// 3) scatter into sorted slots.  Ps occupy [0,m), P occupy [m,m+n).
// ---------------------------------------------------------------------------
__global__ void scatter_kernel(const float* __restrict__ P,
                               const float* __restrict__ Ps, int n, int m) {
    int i = blockIdx.x * blockDim.x + threadIdx.x;
    if (i < m) {
        float x = Ps[3 * i], y = Ps[3 * i + 1], z = Ps[3 * i + 2];
        int c = cellA(x, y, z);
        unsigned int slot = g_blockOff[c >> 10] + g_meta[c].x +
                            atomicAdd(&g_cursor[c], 1u);
        g_sp[slot] = make_float4(x, y, z, __uint_as_float((unsigned int)i));
    } else if (i < m + n) {
        int j = i - m;
        float x = P[3 * j], y = P[3 * j + 1], z = P[3 * j + 2];
        int c = NCA + cellB(x, y, z);
        unsigned int slot = g_blockOff[c >> 10] + g_meta[c].x +
                            atomicAdd(&g_cursor[c], 1u);
        g_sp[slot] = make_float4(x, y, z, __uint_as_float((unsigned int)j));
    }
}

// ---------------------------------------------------------------------------
// 4) nearest-neighbor query: ONE WARP PER QUERY.
//    w <  m : Ps point, min-only, searches grid B (float path).
//    w >= m : P point, min+argmin, searches grid A (u64 path).
//    Phase 1: 3x3x3 box; row metadata prefetched by lanes 0..8 (shfl bcast);
//             lanes stride candidates in each contiguous row-run.
//    Fallback (warp-uniform, ~2% of queries): brute-force scan of the whole
//    opposing target array (contiguous in g_sp), coalesced.  No ring walks.
//    Bound: box is complete iff best_d < h*0.999 - o
//           (o = query overflow beyond the clamped domain).
// ---------------------------------------------------------------------------
__global__ __launch_bounds__(256)
void query_kernel(const float* __restrict__ prob, int n, int m) {
    const int w = (blockIdx.x * blockDim.x + threadIdx.x) >> 5;
    const int lane = threadIdx.x & 31;
    const int total = n + m;
    if (w >= total) return;

    const float4 q = g_sp[w];
    const bool isB = (w < m);

    const int   Gq    = isB ? GB : GA;
    const float invh  = isB ? INVHB : INVHA;
    const float h     = isB ? CELLHB : CELLHA;
    const int   tbase = isB ? NCA : 0;
    // brute-force range: the whole opposing target array in g_sp
    const unsigned int bf0 = isB ? (unsigned int)m : 0u;
    const unsigned int bf1 = isB ? (unsigned int)(m + n) : (unsigned int)m;

    const int cx = cellCoordG(q.x, invh, Gq);
    const int cy = cellCoordG(q.y, invh, Gq);
    const int cz = cellCoordG(q.z, invh, Gq);
    const float o = fmaxf(fmaxf(fabsf(q.x), fmaxf(fabsf(q.y), fabsf(q.z))) - LHALF, 0.0f);
    const float bnd = h * 0.999f - o;          // box completeness radius

    // ---- Phase 1 metadata prefetch: up to 9 row ranges via lanes 0..8
    const int x0 = max(cx - 1, 0), x1 = min(cx + 1, Gq - 1);
    const int y0 = max(cy - 1, 0), y1 = min(cy + 1, Gq - 1);
    const int z0 = max(cz - 1, 0), z1 = min(cz + 1, Gq - 1);
    const int ny = y1 - y0 + 1;
    const int nrows = (z1 - z0 + 1) * ny;

    unsigned int rr0 = 0, rr1 = 0;
    if (lane < nrows) {
        const int rz = lane / ny;
        const int ry = lane - rz * ny;
        const int rowb = tbase + ((z0 + rz) * Gq + (y0 + ry)) * Gq;
        rr0 = cellRange(rowb + x0).x;
        rr1 = cellRange(rowb + x1).y;
    }

    if (isB) {
        // ================= min-only (float) =================
        float best = CUDART_INF_F;
        for (int j = 0; j < nrows; j++) {
            const unsigned int r0 = __shfl_sync(0xFFFFFFFFu, rr0, j);
            const unsigned int r1 = __shfl_sync(0xFFFFFFFFu, rr1, j);
            for (unsigned int v = r0 + lane; v < r1; v += 32) {
                const float4 tp = g_sp[v];
                float ddx = q.x - tp.x;
                float ddy = q.y - tp.y;
                float ddz = q.z - tp.z;
                best = fminf(best, fmaf(ddx, ddx, fmaf(ddy, ddy, ddz * ddz)));
            }
        }
        #pragma unroll
        for (int off = 16; off > 0; off >>= 1)
            best = fminf(best, __shfl_xor_sync(0xFFFFFFFFu, best, off));

        // warp-uniform fallback: brute-force whole target array
        if (!(bnd > 0.0f && best <= bnd * bnd)) {
            for (unsigned int v = bf0 + lane; v < bf1; v += 32) {
                const float4 tp = g_sp[v];
                float ddx = q.x - tp.x;
                float ddy = q.y - tp.y;
                float ddz = q.z - tp.z;
                best = fminf(best, fmaf(ddx, ddx, fmaf(ddy, ddy, ddz * ddz)));
            }
            #pragma unroll
            for (int off = 16; off > 0; off >>= 1)
                best = fminf(best, __shfl_xor_sync(0xFFFFFFFFu, best, off));
        }

        if (lane == 0) {
            const unsigned int qorig = __float_as_uint(q.w);
            g_term[qorig] = sqrtf(best) * __ldg(&prob[qorig]);   // s->o term
        }
    } else {
        // ================= min + argmin (u64 packed) =================
        unsigned long long best = 0xFFFFFFFFFFFFFFFFull;   // (d2_bits<<32)|idx
        for (int j = 0; j < nrows; j++) {
            const unsigned int r0 = __shfl_sync(0xFFFFFFFFu, rr0, j);
            const unsigned int r1 = __shfl_sync(0xFFFFFFFFu, rr1, j);
            for (unsigned int v = r0 + lane; v < r1; v += 32) {
                const float4 tp = g_sp[v];
                float ddx = q.x - tp.x;
                float ddy = q.y - tp.y;
                float ddz = q.z - tp.z;
                float d2 = fmaf(ddx, ddx, fmaf(ddy, ddy, ddz * ddz));
                unsigned long long pk =
                    ((unsigned long long)__float_as_uint(d2) << 32) |
                    (unsigned long long)__float_as_uint(tp.w);
                if (pk < best) best = pk;
            }
        }
        #pragma unroll
        for (int off = 16; off > 0; off >>= 1) {
            unsigned long long ob = __shfl_xor_sync(0xFFFFFFFFu, best, off);
            if (ob < best) best = ob;
        }
        float bestd2 = __uint_as_float((unsigned int)(best >> 32));

        // warp-uniform fallback: brute-force whole target array
        if (!(bnd > 0.0f && bestd2 <= bnd * bnd)) {
            for (unsigned int v = bf0 + lane; v < bf1; v += 32) {
                const float4 tp = g_sp[v];
                float ddx = q.x - tp.x;
                float ddy = q.y - tp.y;
                float ddz = q.z - tp.z;
                float d2 = fmaf(ddx, ddx, fmaf(ddy, ddy, ddz * ddz));
                unsigned long long pk =
                    ((unsigned long long)__float_as_uint(d2) << 32) |
                    (unsigned long long)__float_as_uint(tp.w);
                if (pk < best) best = pk;
            }
            #pragma unroll
            for (int off = 16; off > 0; off >>= 1) {
                unsigned long long ob = __shfl_xor_sync(0xFFFFFFFFu, best, off);
                if (ob < best) best = ob;
            }
        }

        if (lane == 0) {
            const float d = sqrtf(__uint_as_float((unsigned int)(best >> 32)));
            const unsigned int widx = (unsigned int)(best & 0xFFFFFFFFu);
            const unsigned int qorig = __float_as_uint(q.w);
            g_term[m + qorig] = d * __ldg(&prob[widx]);          // o->s term
        }
    }
}

// ---------------------------------------------------------------------------
// 5) deterministic fixed-order sum + fused final; resets cursors for replay.
// ---------------------------------------------------------------------------
__global__ __launch_bounds__(256)
void reduce_kernel(int total, float* __restrict__ out) {
    __shared__ float ssum[256];
    __shared__ bool isLast;
    const int stride = gridDim.x * blockDim.x;
    const int tid0 = blockIdx.x * blockDim.x + threadIdx.x;

    for (int i = tid0; i < NCT_PAD; i += stride) g_cursor[i] = 0u;

    float sum = 0.0f;
    for (int i = tid0; i < total; i += stride)
        sum += g_term[i];

    ssum[threadIdx.x] = sum;
    __syncthreads();
    for (int off = 128; off > 0; off >>= 1) {
        if (threadIdx.x < off) ssum[threadIdx.x] += ssum[threadIdx.x + off];
        __syncthreads();
    }
    if (threadIdx.x == 0) {
        g_partials[blockIdx.x] = ssum[0];
        __threadfence();
        int t = atomicAdd(&g_done, 1);
        isLast = (t == (int)gridDim.x - 1);
    }
    __syncthreads();

    if (isLast) {
        __threadfence();
        volatile float* gp = g_partials;
        float v = (threadIdx.x < (int)gridDim.x) ? gp[threadIdx.x] : 0.0f;
        ssum[threadIdx.x] = v;
        __syncthreads();
        for (int off = 128; off > 0; off >>= 1) {
            if (threadIdx.x < off) ssum[threadIdx.x] += ssum[threadIdx.x + off];
            __syncthreads();
        }
        if (threadIdx.x == 0) {
            out[0] = ssum[0];
            g_done = 0;
        }
    }
}

// ---------------------------------------------------------------------------
// Launch: 5 kernels.
// ---------------------------------------------------------------------------
extern "C" void kernel_launch(void* const* d_in, const int* in_sizes, int n_in,
                              void* d_out, int out_size) {
    const float* P    = (const float*)d_in[0];
    const float* Ps   = (const float*)d_in[1];
    const float* prob = (const float*)d_in[2];
    float* out = (float*)d_out;

    const int n = in_sizes[0] / 3;   // 30000
    const int m = in_sizes[1] / 3;   // 10000
    const int total = n + m;
    const int nb = (total + 255) / 256;

    count_kernel<<<nb, 256>>>(P, Ps, n, m);
    scan_kernel<<<SCAN_NB, SCAN_T>>>();
    scatter_kernel<<<nb, 256>>>(P, Ps, n, m);
    query_kernel<<<(total * 32 + 255) / 256, 256>>>(prob, n, m);
    reduce_kernel<<<NB_RED, 256>>>(total, out);
}